// round 4
// baseline (speedup 1.0000x reference)
#include <cuda_runtime.h>
#include <math.h>
#include <stdint.h>

#define BB   2
#define SS   2048
#define DD   512
#define WW   64
#define MR   (BB*SS)     // 4096 rows

// Scratch (device globals — no allocation allowed)
__device__ float g_q[MR*DD];
__device__ float g_k[MR*DD];
__device__ float g_v[MR*DD];
__device__ float g_r[MR*DD];
__device__ float g_att[MR*DD];
__device__ float g_proj[MR*DD];

__device__ __forceinline__ uint32_t tf32r(float f) {
    uint32_t u; asm("cvt.rna.tf32.f32 %0, %1;" : "=r"(u) : "f"(f)); return u;
}

__device__ __forceinline__ void mma_tf32(float* c, const uint32_t* a, const uint32_t* b) {
    asm("mma.sync.aligned.m16n8k8.row.col.f32.tf32.tf32.f32 "
        "{%0,%1,%2,%3}, {%4,%5,%6,%7}, {%8,%9}, {%0,%1,%2,%3};"
        : "+f"(c[0]), "+f"(c[1]), "+f"(c[2]), "+f"(c[3])
        : "r"(a[0]), "r"(a[1]), "r"(a[2]), "r"(a[3]), "r"(b[0]), "r"(b[1]));
}

// ===========================================================================
// tf32 tensor-core GEMM: C[4096,512] = A[4096,512] @ W[512,512] + bias
// CTA tile 128x128, BK=32, 256 threads (8 warps, warp tile 32x64).
// ===========================================================================
#define SKA 36
#define SKB 132

__device__ __forceinline__ void gemm_mma(const float* __restrict__ A,
                                         const float* __restrict__ W,
                                         const float* __restrict__ bias,
                                         float* __restrict__ C)
{
    __shared__ float As[128 * SKA];
    __shared__ float Bs[32 * SKB];

    const int tid  = threadIdx.x;
    const int lane = tid & 31;
    const int wid  = tid >> 5;
    const int g    = lane >> 2;
    const int tg   = lane & 3;
    const int m0   = blockIdx.y * 128;
    const int n0   = blockIdx.x * 128;
    const int wm   = (wid >> 1) * 32;
    const int wn   = (wid & 1) * 64;

    const int arow = tid >> 3;
    const int acol = (tid & 7) * 4;
    const int brow = tid >> 5;
    const int bcol = (tid & 31) * 4;

    const float* Ab = A + (m0 + arow) * DD + acol;
    const float* Wb = W + brow * DD + n0 + bcol;

    float4 pa[4], pb[4];
#pragma unroll
    for (int i = 0; i < 4; i++) {
        pa[i] = *(const float4*)(Ab + i * 32 * DD);
        pb[i] = *(const float4*)(Wb + i * 8 * DD);
    }

    float acc[2][8][4];
#pragma unroll
    for (int mt = 0; mt < 2; mt++)
#pragma unroll
        for (int nt = 0; nt < 8; nt++)
#pragma unroll
            for (int q = 0; q < 4; q++) acc[mt][nt][q] = 0.f;

    for (int ch = 0; ch < 16; ch++) {
        __syncthreads();
#pragma unroll
        for (int i = 0; i < 4; i++) {
            uint4 ua;
            ua.x = tf32r(pa[i].x); ua.y = tf32r(pa[i].y);
            ua.z = tf32r(pa[i].z); ua.w = tf32r(pa[i].w);
            *(uint4*)&As[(arow + 32 * i) * SKA + acol] = ua;
            uint4 ub;
            ub.x = tf32r(pb[i].x); ub.y = tf32r(pb[i].y);
            ub.z = tf32r(pb[i].z); ub.w = tf32r(pb[i].w);
            *(uint4*)&Bs[(brow + 8 * i) * SKB + bcol] = ub;
        }
        __syncthreads();

        if (ch < 15) {
            const float* Ab2 = Ab + (ch + 1) * 32;
            const float* Wb2 = Wb + (ch + 1) * 32 * DD;
#pragma unroll
            for (int i = 0; i < 4; i++) {
                pa[i] = *(const float4*)(Ab2 + i * 32 * DD);
                pb[i] = *(const float4*)(Wb2 + i * 8 * DD);
            }
        }

#pragma unroll
        for (int kk = 0; kk < 4; kk++) {
            const int kb = kk * 8;
            uint32_t af[2][4], bf[8][2];
#pragma unroll
            for (int mt = 0; mt < 2; mt++) {
                const int m = wm + mt * 16 + g;
                af[mt][0] = __float_as_uint(As[m * SKA + kb + tg]);
                af[mt][1] = __float_as_uint(As[(m + 8) * SKA + kb + tg]);
                af[mt][2] = __float_as_uint(As[m * SKA + kb + tg + 4]);
                af[mt][3] = __float_as_uint(As[(m + 8) * SKA + kb + tg + 4]);
            }
#pragma unroll
            for (int nt = 0; nt < 8; nt++) {
                const int n = wn + nt * 8 + g;
                bf[nt][0] = __float_as_uint(Bs[(kb + tg) * SKB + n]);
                bf[nt][1] = __float_as_uint(Bs[(kb + tg + 4) * SKB + n]);
            }
#pragma unroll
            for (int mt = 0; mt < 2; mt++)
#pragma unroll
                for (int nt = 0; nt < 8; nt++)
                    mma_tf32(acc[mt][nt], af[mt], bf[nt]);
        }
    }

#pragma unroll
    for (int nt = 0; nt < 8; nt++) {
        const int n = n0 + wn + nt * 8 + 2 * tg;
        const float2 bb = *(const float2*)&bias[n];
#pragma unroll
        for (int mt = 0; mt < 2; mt++) {
            const int m = m0 + wm + mt * 16 + g;
            float2 v0 = make_float2(acc[mt][nt][0] + bb.x, acc[mt][nt][1] + bb.y);
            float2 v1 = make_float2(acc[mt][nt][2] + bb.x, acc[mt][nt][3] + bb.y);
            *(float2*)&C[m * DD + n]       = v0;
            *(float2*)&C[(m + 8) * DD + n] = v1;
        }
    }
}

__global__ void __launch_bounds__(256, 2) k_gemm_qkvr(
    const float* __restrict__ x,
    const float* Wq, const float* bq,
    const float* Wk, const float* bk,
    const float* Wv, const float* bv,
    const float* Wr, const float* br)
{
    const float* W; const float* bias; float* C;
    switch (blockIdx.z) {
        case 0:  W = Wq; bias = bq; C = g_q; break;
        case 1:  W = Wk; bias = bk; C = g_k; break;
        case 2:  W = Wv; bias = bv; C = g_v; break;
        default: W = Wr; bias = br; C = g_r; break;
    }
    gemm_mma(x, W, bias, C);
}

__global__ void __launch_bounds__(256, 2) k_gemm_proj(
    const float* __restrict__ Wo, const float* __restrict__ bo)
{
    gemm_mma(g_att, Wo, bo, g_proj);
}

// ===========================================================================
// Tensor-core local attention. 32 queries/block (128 blocks, 256 threads).
// Window keys: 96 padded (valid band: m <= col <= m+63, jg >= 0).
//   Phase 1: S[32][96] = Q @ K^T via mma tf32, K chunked over d (4 x 128).
//   Phase 2: mask + softmax in smem.
//   Phase 3: out = P @ V via block-cooperative FFMA (P broadcast from smem).
// ===========================================================================
#define QB    32
#define KWIN  96
#define AST   132        // Qs/Ks row stride (floats)
#define PST   97         // Ps row stride

#define QS_F   (QB * AST)            // 4224 floats
#define KS_F   (KWIN * AST)          // 12672 floats
#define PS_F   (QB * PST)            // 3104 floats
#define ATTN_SMEM ((QS_F + KS_F + PS_F) * 4)   // 80000 bytes

__global__ void __launch_bounds__(256) k_attn()
{
    extern __shared__ float smf[];
    float* Qs = smf;
    float* Ks = smf + QS_F;
    float* Ps = smf + QS_F + KS_F;

    const int t    = threadIdx.x;
    const int lane = t & 31;
    const int warp = t >> 5;
    const int g    = lane >> 2;
    const int tg   = lane & 3;

    const int q0   = blockIdx.x * QB;
    const int b    = q0 / SS;
    const int s0   = q0 - b * SS;
    const int base = b * SS;

    // warp tiling for scores: mt = warp>>2 (2 m-tiles), nq = warp&3 (3 n-tiles each)
    const int mt = warp >> 2;
    const int nq = warp & 3;

    float acc[3][4];
#pragma unroll
    for (int i = 0; i < 3; i++)
#pragma unroll
        for (int q = 0; q < 4; q++) acc[i][q] = 0.f;

    for (int ch = 0; ch < 4; ch++) {
        const int koff = ch * 128;
        __syncthreads();   // guard Ks/Qs reuse from previous chunk's MMA reads
        // Q chunk: 32 rows x 128 floats = 1024 float4
#pragma unroll
        for (int i = 0; i < 4; i++) {
            const int f = t + 256 * i;
            const int row = f >> 5, dg = f & 31;
            float4 v = *(const float4*)&g_q[(q0 + row) * DD + koff + dg * 4];
            uint4 u; u.x = tf32r(v.x); u.y = tf32r(v.y); u.z = tf32r(v.z); u.w = tf32r(v.w);
            *(uint4*)&Qs[row * AST + dg * 4] = u;
        }
        // K chunk: 96 rows x 128 floats = 3072 float4 (clamped row index)
#pragma unroll
        for (int i = 0; i < 12; i++) {
            const int f = t + 256 * i;
            const int row = f >> 5, dg = f & 31;
            int jg = s0 - 63 + row;
            jg = jg < 0 ? 0 : (jg > SS - 1 ? SS - 1 : jg);
            float4 v = *(const float4*)&g_k[(base + jg) * DD + koff + dg * 4];
            uint4 u; u.x = tf32r(v.x); u.y = tf32r(v.y); u.z = tf32r(v.z); u.w = tf32r(v.w);
            *(uint4*)&Ks[row * AST + dg * 4] = u;
        }
        __syncthreads();

#pragma unroll
        for (int ks = 0; ks < 16; ks++) {
            const int kb = ks * 8;
            const int m = mt * 16 + g;
            uint32_t af[4];
            af[0] = __float_as_uint(Qs[m * AST + kb + tg]);
            af[1] = __float_as_uint(Qs[(m + 8) * AST + kb + tg]);
            af[2] = __float_as_uint(Qs[m * AST + kb + tg + 4]);
            af[3] = __float_as_uint(Qs[(m + 8) * AST + kb + tg + 4]);
#pragma unroll
            for (int ntl = 0; ntl < 3; ntl++) {
                const int n = (nq * 3 + ntl) * 8 + g;
                uint32_t bf[2];
                bf[0] = __float_as_uint(Ks[n * AST + kb + tg]);
                bf[1] = __float_as_uint(Ks[n * AST + kb + tg + 4]);
                mma_tf32(acc[ntl], af, bf);
            }
        }
    }
    __syncthreads();

    // store scores
#pragma unroll
    for (int ntl = 0; ntl < 3; ntl++) {
        const int colb = (nq * 3 + ntl) * 8 + 2 * tg;
        const int m = mt * 16 + g;
        Ps[m * PST + colb]           = acc[ntl][0];
        Ps[m * PST + colb + 1]       = acc[ntl][1];
        Ps[(m + 8) * PST + colb]     = acc[ntl][2];
        Ps[(m + 8) * PST + colb + 1] = acc[ntl][3];
    }
    __syncthreads();

    // mask + softmax: warp handles 4 rows
    const float scale = 0.044194173824159216f;   // 1/sqrt(512)
#pragma unroll
    for (int rr = 0; rr < 4; rr++) {
        const int r = warp * 4 + rr;
        float v[3];
#pragma unroll
        for (int i = 0; i < 3; i++) {
            const int col = lane + 32 * i;
            const bool valid = (col >= r) && (col <= r + 63) && (s0 - 63 + col >= 0);
            v[i] = valid ? Ps[r * PST + col] * scale : -1e9f;
        }
        float mx = fmaxf(v[0], fmaxf(v[1], v[2]));
#pragma unroll
        for (int off = 16; off; off >>= 1)
            mx = fmaxf(mx, __shfl_xor_sync(0xffffffffu, mx, off));
        float e[3];
        float sum = 0.f;
#pragma unroll
        for (int i = 0; i < 3; i++) { e[i] = expf(v[i] - mx); sum += e[i]; }
#pragma unroll
        for (int off = 16; off; off >>= 1)
            sum += __shfl_xor_sync(0xffffffffu, sum, off);
        const float inv = 1.0f / sum;
#pragma unroll
        for (int i = 0; i < 3; i++)
            Ps[r * PST + lane + 32 * i] = e[i] * inv;
    }
    __syncthreads();

    // AV: thread -> dim group (t&127)*4, m-half (t>>7)*16
    const int d  = (t & 127) * 4;
    const int mh = (t >> 7) * 16;
    float4 ov[16];
#pragma unroll
    for (int m = 0; m < 16; m++) ov[m] = make_float4(0.f, 0.f, 0.f, 0.f);

    for (int j = 0; j < KWIN; j++) {
        int jg = s0 - 63 + j;
        jg = jg < 0 ? 0 : (jg > SS - 1 ? SS - 1 : jg);
        const float4 vv = *(const float4*)&g_v[(base + jg) * DD + d];
#pragma unroll
        for (int m = 0; m < 16; m++) {
            const float p = Ps[(mh + m) * PST + j];
            ov[m].x += p * vv.x; ov[m].y += p * vv.y;
            ov[m].z += p * vv.z; ov[m].w += p * vv.w;
        }
    }
#pragma unroll
    for (int m = 0; m < 16; m++)
        *(float4*)&g_att[(q0 + mh + m) * DD + d] = ov[m];
}

// ===========================================================================
// Dual LayerNorm + add + exact GELU. One block (256 threads) per row.
// ===========================================================================
__global__ void __launch_bounds__(256) k_ln_gelu(
    const float* __restrict__ gamma, const float* __restrict__ beta,
    float* __restrict__ out)
{
    const int row = blockIdx.x;
    const int t   = threadIdx.x;
    const float* p = g_proj + row * DD;
    const float* r = g_r    + row * DD;

    float p0 = p[t], p1 = p[t + 256];
    float r0 = r[t], r1 = r[t + 256];

    float sp = p0 + p1, spp = p0 * p0 + p1 * p1;
    float sr = r0 + r1, srr = r0 * r0 + r1 * r1;

    __shared__ float red[8][4];
#pragma unroll
    for (int off = 16; off; off >>= 1) {
        sp  += __shfl_xor_sync(0xffffffffu, sp,  off);
        spp += __shfl_xor_sync(0xffffffffu, spp, off);
        sr  += __shfl_xor_sync(0xffffffffu, sr,  off);
        srr += __shfl_xor_sync(0xffffffffu, srr, off);
    }
    const int lane = t & 31, w = t >> 5;
    if (lane == 0) { red[w][0] = sp; red[w][1] = spp; red[w][2] = sr; red[w][3] = srr; }
    __syncthreads();
    float Sp = 0.f, Spp = 0.f, Sr = 0.f, Srr = 0.f;
#pragma unroll
    for (int i = 0; i < 8; i++) {
        Sp += red[i][0]; Spp += red[i][1]; Sr += red[i][2]; Srr += red[i][3];
    }

    const float invD = 1.0f / (float)DD;
    const float mup = Sp * invD;
    const float ip  = rsqrtf(Spp * invD - mup * mup + 1e-5f);
    const float mur = Sr * invD;
    const float ir  = rsqrtf(Srr * invD - mur * mur + 1e-5f);

    const float ga0 = gamma[t], ga1 = gamma[t + 256];
    const float be0 = beta[t],  be1 = beta[t + 256];

    const float y0 = (p0 - mup) * ip * ga0 + be0 + (r0 - mur) * ir * ga0 + be0;
    const float y1 = (p1 - mup) * ip * ga1 + be1 + (r1 - mur) * ir * ga1 + be1;

    out[row * DD + t]       = y0 * normcdff(y0);
    out[row * DD + t + 256] = y1 * normcdff(y1);
}

// ===========================================================================
extern "C" void kernel_launch(void* const* d_in, const int* in_sizes, int n_in,
                              void* d_out, int out_size)
{
    const float* x     = (const float*)d_in[0];
    const float* Wq    = (const float*)d_in[1];
    const float* bq    = (const float*)d_in[2];
    const float* Wk    = (const float*)d_in[3];
    const float* bk    = (const float*)d_in[4];
    const float* Wv    = (const float*)d_in[5];
    const float* bv    = (const float*)d_in[6];
    const float* Wo    = (const float*)d_in[7];
    const float* bo    = (const float*)d_in[8];
    const float* Wr    = (const float*)d_in[9];
    const float* br    = (const float*)d_in[10];
    const float* gamma = (const float*)d_in[11];
    const float* beta  = (const float*)d_in[12];
    float* out = (float*)d_out;

    static int attr_done = 0;
    if (!attr_done) {
        cudaFuncSetAttribute(k_attn, cudaFuncAttributeMaxDynamicSharedMemorySize,
                             ATTN_SMEM);
        attr_done = 1;
    }

    k_gemm_qkvr<<<dim3(4, 32, 4), 256>>>(x, Wq, bq, Wk, bk, Wv, bv, Wr, br);

    k_attn<<<MR / QB, 256, ATTN_SMEM>>>();

    k_gemm_proj<<<dim3(4, 32, 1), 256>>>(Wo, bo);

    k_ln_gelu<<<MR, 256>>>(gamma, beta, out);
}

// round 5
// speedup vs baseline: 1.0960x; 1.0960x over previous
#include <cuda_runtime.h>
#include <math.h>
#include <stdint.h>

#define BB   2
#define SS   2048
#define DD   512
#define WW   64
#define MR   (BB*SS)     // 4096 rows

// Scratch (device globals — no allocation allowed)
__device__ float g_q[MR*DD];
__device__ float g_k[MR*DD];
__device__ float g_v[MR*DD];
__device__ float g_r[MR*DD];
__device__ float g_att[MR*DD];
__device__ float g_proj[MR*DD];

__device__ __forceinline__ uint32_t tf32r(float f) {
    uint32_t u; asm("cvt.rna.tf32.f32 %0, %1;" : "=r"(u) : "f"(f)); return u;
}

__device__ __forceinline__ void mma_tf32(float* c, const uint32_t* a, const uint32_t* b) {
    asm("mma.sync.aligned.m16n8k8.row.col.f32.tf32.tf32.f32 "
        "{%0,%1,%2,%3}, {%4,%5,%6,%7}, {%8,%9}, {%0,%1,%2,%3};"
        : "+f"(c[0]), "+f"(c[1]), "+f"(c[2]), "+f"(c[3])
        : "r"(a[0]), "r"(a[1]), "r"(a[2]), "r"(a[3]), "r"(b[0]), "r"(b[1]));
}

// ===========================================================================
// tf32 tensor-core GEMM: C[4096,512] = A[4096,512] @ W[512,512] + bias
// CTA tile 128x128, BK=32, 256 threads (8 warps, warp tile 32x64).
// Double-buffered smem: one __syncthreads per chunk, STS overlaps compute.
// ===========================================================================
#define SKA 36
#define SKB 132
#define AS_F (128 * SKA)            // 4608 floats per buffer
#define BS_F (32 * SKB)             // 4224 floats per buffer
#define GEMM_SMEM ((2 * (AS_F + BS_F)) * 4)   // 70656 bytes

__device__ __forceinline__ void gemm_mma(const float* __restrict__ A,
                                         const float* __restrict__ W,
                                         const float* __restrict__ bias,
                                         float* __restrict__ C)
{
    extern __shared__ float dsm[];
    float* As = dsm;                 // 2 buffers
    float* Bs = dsm + 2 * AS_F;      // 2 buffers

    const int tid  = threadIdx.x;
    const int lane = tid & 31;
    const int wid  = tid >> 5;
    const int g    = lane >> 2;
    const int tg   = lane & 3;
    const int m0   = blockIdx.y * 128;
    const int n0   = blockIdx.x * 128;
    const int wm   = (wid >> 1) * 32;
    const int wn   = (wid & 1) * 64;

    const int arow = tid >> 3;
    const int acol = (tid & 7) * 4;
    const int brow = tid >> 5;
    const int bcol = (tid & 31) * 4;

    const float* Ab = A + (m0 + arow) * DD + acol;
    const float* Wb = W + brow * DD + n0 + bcol;

    float4 pa[4], pb[4];
#pragma unroll
    for (int i = 0; i < 4; i++) {
        pa[i] = *(const float4*)(Ab + i * 32 * DD);
        pb[i] = *(const float4*)(Wb + i * 8 * DD);
    }

    float acc[2][8][4];
#pragma unroll
    for (int mt = 0; mt < 2; mt++)
#pragma unroll
        for (int nt = 0; nt < 8; nt++)
#pragma unroll
            for (int q = 0; q < 4; q++) acc[mt][nt][q] = 0.f;

    // STS chunk 0 into buffer 0
#pragma unroll
    for (int i = 0; i < 4; i++) {
        uint4 ua;
        ua.x = tf32r(pa[i].x); ua.y = tf32r(pa[i].y);
        ua.z = tf32r(pa[i].z); ua.w = tf32r(pa[i].w);
        *(uint4*)&As[(arow + 32 * i) * SKA + acol] = ua;
        uint4 ub;
        ub.x = tf32r(pb[i].x); ub.y = tf32r(pb[i].y);
        ub.z = tf32r(pb[i].z); ub.w = tf32r(pb[i].w);
        *(uint4*)&Bs[(brow + 8 * i) * SKB + bcol] = ub;
    }
    __syncthreads();

    for (int ch = 0; ch < 16; ch++) {
        const int cur = ch & 1;
        const float* Asb = As + cur * AS_F;
        const float* Bsb = Bs + cur * BS_F;

        // prefetch chunk ch+1 from gmem (overlaps compute below)
        if (ch < 15) {
            const float* Ab2 = Ab + (ch + 1) * 32;
            const float* Wb2 = Wb + (ch + 1) * 32 * DD;
#pragma unroll
            for (int i = 0; i < 4; i++) {
                pa[i] = *(const float4*)(Ab2 + i * 32 * DD);
                pb[i] = *(const float4*)(Wb2 + i * 8 * DD);
            }
        }

#pragma unroll
        for (int kk = 0; kk < 4; kk++) {
            const int kb = kk * 8;
            uint32_t af[2][4], bf[8][2];
#pragma unroll
            for (int mt = 0; mt < 2; mt++) {
                const int m = wm + mt * 16 + g;
                af[mt][0] = __float_as_uint(Asb[m * SKA + kb + tg]);
                af[mt][1] = __float_as_uint(Asb[(m + 8) * SKA + kb + tg]);
                af[mt][2] = __float_as_uint(Asb[m * SKA + kb + tg + 4]);
                af[mt][3] = __float_as_uint(Asb[(m + 8) * SKA + kb + tg + 4]);
            }
#pragma unroll
            for (int nt = 0; nt < 8; nt++) {
                const int n = wn + nt * 8 + g;
                bf[nt][0] = __float_as_uint(Bsb[(kb + tg) * SKB + n]);
                bf[nt][1] = __float_as_uint(Bsb[(kb + tg + 4) * SKB + n]);
            }
#pragma unroll
            for (int mt = 0; mt < 2; mt++)
#pragma unroll
                for (int nt = 0; nt < 8; nt++)
                    mma_tf32(acc[mt][nt], af[mt], bf[nt]);
        }

        // STS chunk ch+1 into the other buffer, then single sync
        if (ch < 15) {
            float* Asn = As + (1 - cur) * AS_F;
            float* Bsn = Bs + (1 - cur) * BS_F;
#pragma unroll
            for (int i = 0; i < 4; i++) {
                uint4 ua;
                ua.x = tf32r(pa[i].x); ua.y = tf32r(pa[i].y);
                ua.z = tf32r(pa[i].z); ua.w = tf32r(pa[i].w);
                *(uint4*)&Asn[(arow + 32 * i) * SKA + acol] = ua;
                uint4 ub;
                ub.x = tf32r(pb[i].x); ub.y = tf32r(pb[i].y);
                ub.z = tf32r(pb[i].z); ub.w = tf32r(pb[i].w);
                *(uint4*)&Bsn[(brow + 8 * i) * SKB + bcol] = ub;
            }
            __syncthreads();
        }
    }

    // epilogue: bias + direct STG.64
#pragma unroll
    for (int nt = 0; nt < 8; nt++) {
        const int n = n0 + wn + nt * 8 + 2 * tg;
        const float2 bb = *(const float2*)&bias[n];
#pragma unroll
        for (int mt = 0; mt < 2; mt++) {
            const int m = m0 + wm + mt * 16 + g;
            float2 v0 = make_float2(acc[mt][nt][0] + bb.x, acc[mt][nt][1] + bb.y);
            float2 v1 = make_float2(acc[mt][nt][2] + bb.x, acc[mt][nt][3] + bb.y);
            *(float2*)&C[m * DD + n]       = v0;
            *(float2*)&C[(m + 8) * DD + n] = v1;
        }
    }
}

__global__ void __launch_bounds__(256, 2) k_gemm_qkvr(
    const float* __restrict__ x,
    const float* Wq, const float* bq,
    const float* Wk, const float* bk,
    const float* Wv, const float* bv,
    const float* Wr, const float* br)
{
    const float* W; const float* bias; float* C;
    switch (blockIdx.z) {
        case 0:  W = Wq; bias = bq; C = g_q; break;
        case 1:  W = Wk; bias = bk; C = g_k; break;
        case 2:  W = Wv; bias = bv; C = g_v; break;
        default: W = Wr; bias = br; C = g_r; break;
    }
    gemm_mma(x, W, bias, C);
}

__global__ void __launch_bounds__(256, 2) k_gemm_proj(
    const float* __restrict__ Wo, const float* __restrict__ bo)
{
    gemm_mma(g_att, Wo, bo, g_proj);
}

// ===========================================================================
// Local windowed attention: one warp per query, 32 warps (1024 thr) per block
// so neighboring warps hit the same K/V window rows while hot in L1.
// ===========================================================================
__global__ void __launch_bounds__(1024) k_attn()
{
    const int warp = threadIdx.x >> 5;
    const int lane = threadIdx.x & 31;
    const int gq   = blockIdx.x * 32 + warp;
    const int b    = gq / SS;
    const int s    = gq - b * SS;
    const int base = b * SS;

    const float* qrow = g_q + gq * DD;
    float qreg[16];
#pragma unroll
    for (int i = 0; i < 16; i++) qreg[i] = qrow[lane + 32 * i];

    __shared__ float sh[32][WW];
    const int j0 = s - (WW - 1);
    const float scale = 0.044194173824159216f;   // 1/sqrt(512)

    for (int w = 0; w < WW; w++) {
        const int j = j0 + w;
        float part = 0.f;
        if (j >= 0) {
            const float* krow = g_k + (base + j) * DD;
#pragma unroll
            for (int i = 0; i < 16; i++) part += qreg[i] * krow[lane + 32 * i];
        }
#pragma unroll
        for (int off = 16; off; off >>= 1)
            part += __shfl_down_sync(0xffffffffu, part, off);
        if (lane == 0) sh[warp][w] = (j >= 0) ? part * scale : -1e9f;
    }
    __syncwarp();

    float s0 = sh[warp][lane], s1 = sh[warp][lane + 32];
    float mx = fmaxf(s0, s1);
#pragma unroll
    for (int off = 16; off; off >>= 1)
        mx = fmaxf(mx, __shfl_xor_sync(0xffffffffu, mx, off));
    float e0 = expf(s0 - mx), e1 = expf(s1 - mx);
    float sum = e0 + e1;
#pragma unroll
    for (int off = 16; off; off >>= 1)
        sum += __shfl_xor_sync(0xffffffffu, sum, off);
    const float inv = 1.0f / sum;
    sh[warp][lane]      = e0 * inv;
    sh[warp][lane + 32] = e1 * inv;
    __syncwarp();

    float acc[16];
#pragma unroll
    for (int i = 0; i < 16; i++) acc[i] = 0.f;
    for (int w = 0; w < WW; w++) {
        const int j = j0 + w;
        if (j < 0) continue;
        const float p = sh[warp][w];
        const float* vrow = g_v + (base + j) * DD;
#pragma unroll
        for (int i = 0; i < 16; i++) acc[i] += p * vrow[lane + 32 * i];
    }
    float* orow = g_att + gq * DD;
#pragma unroll
    for (int i = 0; i < 16; i++) orow[lane + 32 * i] = acc[i];
}

// ===========================================================================
// Dual LayerNorm + add + exact GELU. One block (256 threads) per row.
// ===========================================================================
__global__ void __launch_bounds__(256) k_ln_gelu(
    const float* __restrict__ gamma, const float* __restrict__ beta,
    float* __restrict__ out)
{
    const int row = blockIdx.x;
    const int t   = threadIdx.x;
    const float* p = g_proj + row * DD;
    const float* r = g_r    + row * DD;

    float p0 = p[t], p1 = p[t + 256];
    float r0 = r[t], r1 = r[t + 256];

    float sp = p0 + p1, spp = p0 * p0 + p1 * p1;
    float sr = r0 + r1, srr = r0 * r0 + r1 * r1;

    __shared__ float red[8][4];
#pragma unroll
    for (int off = 16; off; off >>= 1) {
        sp  += __shfl_xor_sync(0xffffffffu, sp,  off);
        spp += __shfl_xor_sync(0xffffffffu, spp, off);
        sr  += __shfl_xor_sync(0xffffffffu, sr,  off);
        srr += __shfl_xor_sync(0xffffffffu, srr, off);
    }
    const int lane = t & 31, w = t >> 5;
    if (lane == 0) { red[w][0] = sp; red[w][1] = spp; red[w][2] = sr; red[w][3] = srr; }
    __syncthreads();
    float Sp = 0.f, Spp = 0.f, Sr = 0.f, Srr = 0.f;
#pragma unroll
    for (int i = 0; i < 8; i++) {
        Sp += red[i][0]; Spp += red[i][1]; Sr += red[i][2]; Srr += red[i][3];
    }

    const float invD = 1.0f / (float)DD;
    const float mup = Sp * invD;
    const float ip  = rsqrtf(Spp * invD - mup * mup + 1e-5f);
    const float mur = Sr * invD;
    const float ir  = rsqrtf(Srr * invD - mur * mur + 1e-5f);

    const float ga0 = gamma[t], ga1 = gamma[t + 256];
    const float be0 = beta[t],  be1 = beta[t + 256];

    const float y0 = (p0 - mup) * ip * ga0 + be0 + (r0 - mur) * ir * ga0 + be0;
    const float y1 = (p1 - mup) * ip * ga1 + be1 + (r1 - mur) * ir * ga1 + be1;

    out[row * DD + t]       = y0 * normcdff(y0);
    out[row * DD + t + 256] = y1 * normcdff(y1);
}

// ===========================================================================
extern "C" void kernel_launch(void* const* d_in, const int* in_sizes, int n_in,
                              void* d_out, int out_size)
{
    const float* x     = (const float*)d_in[0];
    const float* Wq    = (const float*)d_in[1];
    const float* bq    = (const float*)d_in[2];
    const float* Wk    = (const float*)d_in[3];
    const float* bk    = (const float*)d_in[4];
    const float* Wv    = (const float*)d_in[5];
    const float* bv    = (const float*)d_in[6];
    const float* Wo    = (const float*)d_in[7];
    const float* bo    = (const float*)d_in[8];
    const float* Wr    = (const float*)d_in[9];
    const float* br    = (const float*)d_in[10];
    const float* gamma = (const float*)d_in[11];
    const float* beta  = (const float*)d_in[12];
    float* out = (float*)d_out;

    static int attr_done = 0;
    if (!attr_done) {
        cudaFuncSetAttribute(k_gemm_qkvr, cudaFuncAttributeMaxDynamicSharedMemorySize,
                             GEMM_SMEM);
        cudaFuncSetAttribute(k_gemm_proj, cudaFuncAttributeMaxDynamicSharedMemorySize,
                             GEMM_SMEM);
        attr_done = 1;
    }

    k_gemm_qkvr<<<dim3(4, 32, 4), 256, GEMM_SMEM>>>(x, Wq, bq, Wk, bk, Wv, bv, Wr, br);

    k_attn<<<MR / 32, 1024>>>();

    k_gemm_proj<<<dim3(4, 32, 1), 256, GEMM_SMEM>>>(Wo, bo);

    k_ln_gelu<<<MR, 256>>>(gamma, beta, out);
}

// round 6
// speedup vs baseline: 1.2096x; 1.1036x over previous
#include <cuda_runtime.h>
#include <math.h>
#include <stdint.h>

#define BB   2
#define SS   2048
#define DD   512
#define WW   64
#define MR   (BB*SS)     // 4096 rows

// Scratch (device globals — no allocation allowed)
__device__ float g_q[MR*DD];
__device__ float g_k[MR*DD];
__device__ float g_v[MR*DD];
__device__ float g_r[MR*DD];
__device__ float g_att[MR*DD];
__device__ float g_proj[MR*DD];

__device__ __forceinline__ uint32_t tf32r(float f) {
    uint32_t u; asm("cvt.rna.tf32.f32 %0, %1;" : "=r"(u) : "f"(f)); return u;
}

__device__ __forceinline__ void mma_tf32(float* c, const uint32_t* a, const uint32_t* b) {
    asm("mma.sync.aligned.m16n8k8.row.col.f32.tf32.tf32.f32 "
        "{%0,%1,%2,%3}, {%4,%5,%6,%7}, {%8,%9}, {%0,%1,%2,%3};"
        : "+f"(c[0]), "+f"(c[1]), "+f"(c[2]), "+f"(c[3])
        : "r"(a[0]), "r"(a[1]), "r"(a[2]), "r"(a[3]), "r"(b[0]), "r"(b[1]));
}

// ===========================================================================
// tf32 tensor-core GEMM: C[4096,512] = A[4096,512] @ W[512,512] + bias
// CTA tile 128x128, BK=32, 256 threads (8 warps, warp tile 32x64).
// (R3 version — single buffer, two syncs per chunk; measured fastest.)
// ===========================================================================
#define SKA 36
#define SKB 132

__device__ __forceinline__ void gemm_mma(const float* __restrict__ A,
                                         const float* __restrict__ W,
                                         const float* __restrict__ bias,
                                         float* __restrict__ C)
{
    __shared__ float As[128 * SKA];
    __shared__ float Bs[32 * SKB];

    const int tid  = threadIdx.x;
    const int lane = tid & 31;
    const int wid  = tid >> 5;
    const int g    = lane >> 2;
    const int tg   = lane & 3;
    const int m0   = blockIdx.y * 128;
    const int n0   = blockIdx.x * 128;
    const int wm   = (wid >> 1) * 32;
    const int wn   = (wid & 1) * 64;

    const int arow = tid >> 3;
    const int acol = (tid & 7) * 4;
    const int brow = tid >> 5;
    const int bcol = (tid & 31) * 4;

    const float* Ab = A + (m0 + arow) * DD + acol;
    const float* Wb = W + brow * DD + n0 + bcol;

    float4 pa[4], pb[4];
#pragma unroll
    for (int i = 0; i < 4; i++) {
        pa[i] = *(const float4*)(Ab + i * 32 * DD);
        pb[i] = *(const float4*)(Wb + i * 8 * DD);
    }

    float acc[2][8][4];
#pragma unroll
    for (int mt = 0; mt < 2; mt++)
#pragma unroll
        for (int nt = 0; nt < 8; nt++)
#pragma unroll
            for (int q = 0; q < 4; q++) acc[mt][nt][q] = 0.f;

    for (int ch = 0; ch < 16; ch++) {
        __syncthreads();
#pragma unroll
        for (int i = 0; i < 4; i++) {
            uint4 ua;
            ua.x = tf32r(pa[i].x); ua.y = tf32r(pa[i].y);
            ua.z = tf32r(pa[i].z); ua.w = tf32r(pa[i].w);
            *(uint4*)&As[(arow + 32 * i) * SKA + acol] = ua;
            uint4 ub;
            ub.x = tf32r(pb[i].x); ub.y = tf32r(pb[i].y);
            ub.z = tf32r(pb[i].z); ub.w = tf32r(pb[i].w);
            *(uint4*)&Bs[(brow + 8 * i) * SKB + bcol] = ub;
        }
        __syncthreads();

        if (ch < 15) {
            const float* Ab2 = Ab + (ch + 1) * 32;
            const float* Wb2 = Wb + (ch + 1) * 32 * DD;
#pragma unroll
            for (int i = 0; i < 4; i++) {
                pa[i] = *(const float4*)(Ab2 + i * 32 * DD);
                pb[i] = *(const float4*)(Wb2 + i * 8 * DD);
            }
        }

#pragma unroll
        for (int kk = 0; kk < 4; kk++) {
            const int kb = kk * 8;
            uint32_t af[2][4], bf[8][2];
#pragma unroll
            for (int mt = 0; mt < 2; mt++) {
                const int m = wm + mt * 16 + g;
                af[mt][0] = __float_as_uint(As[m * SKA + kb + tg]);
                af[mt][1] = __float_as_uint(As[(m + 8) * SKA + kb + tg]);
                af[mt][2] = __float_as_uint(As[m * SKA + kb + tg + 4]);
                af[mt][3] = __float_as_uint(As[(m + 8) * SKA + kb + tg + 4]);
            }
#pragma unroll
            for (int nt = 0; nt < 8; nt++) {
                const int n = wn + nt * 8 + g;
                bf[nt][0] = __float_as_uint(Bs[(kb + tg) * SKB + n]);
                bf[nt][1] = __float_as_uint(Bs[(kb + tg + 4) * SKB + n]);
            }
#pragma unroll
            for (int mt = 0; mt < 2; mt++)
#pragma unroll
                for (int nt = 0; nt < 8; nt++)
                    mma_tf32(acc[mt][nt], af[mt], bf[nt]);
        }
    }

#pragma unroll
    for (int nt = 0; nt < 8; nt++) {
        const int n = n0 + wn + nt * 8 + 2 * tg;
        const float2 bb = *(const float2*)&bias[n];
#pragma unroll
        for (int mt = 0; mt < 2; mt++) {
            const int m = m0 + wm + mt * 16 + g;
            float2 v0 = make_float2(acc[mt][nt][0] + bb.x, acc[mt][nt][1] + bb.y);
            float2 v1 = make_float2(acc[mt][nt][2] + bb.x, acc[mt][nt][3] + bb.y);
            *(float2*)&C[m * DD + n]       = v0;
            *(float2*)&C[(m + 8) * DD + n] = v1;
        }
    }
}

// Q/K/V projections only (R projection deferred to overlap the proj phase)
__global__ void __launch_bounds__(256, 2) k_gemm_qkv(
    const float* __restrict__ x,
    const float* Wq, const float* bq,
    const float* Wk, const float* bk,
    const float* Wv, const float* bv)
{
    const float* W; const float* bias; float* C;
    switch (blockIdx.z) {
        case 0:  W = Wq; bias = bq; C = g_q; break;
        case 1:  W = Wk; bias = bk; C = g_k; break;
        default: W = Wv; bias = bv; C = g_v; break;
    }
    gemm_mma(x, W, bias, C);
}

// proj (att@Wo) and r (x@Wr) fused in one launch — fills the half-idle
// proj phase with the independent r work.
__global__ void __launch_bounds__(256, 2) k_gemm_pr(
    const float* __restrict__ x,
    const float* Wo, const float* bo,
    const float* Wr, const float* br)
{
    if (blockIdx.z == 0) gemm_mma(g_att, Wo, bo, g_proj);
    else                 gemm_mma(x,     Wr, br, g_r);
}

// ===========================================================================
// Local windowed attention: one warp per query, 32 warps (1024 thr) per block
// ===========================================================================
__global__ void __launch_bounds__(1024) k_attn()
{
    const int warp = threadIdx.x >> 5;
    const int lane = threadIdx.x & 31;
    const int gq   = blockIdx.x * 32 + warp;
    const int b    = gq / SS;
    const int s    = gq - b * SS;
    const int base = b * SS;

    const float* qrow = g_q + gq * DD;
    float qreg[16];
#pragma unroll
    for (int i = 0; i < 16; i++) qreg[i] = qrow[lane + 32 * i];

    __shared__ float sh[32][WW];
    const int j0 = s - (WW - 1);
    const float scale = 0.044194173824159216f;   // 1/sqrt(512)

    for (int w = 0; w < WW; w++) {
        const int j = j0 + w;
        float part = 0.f;
        if (j >= 0) {
            const float* krow = g_k + (base + j) * DD;
#pragma unroll
            for (int i = 0; i < 16; i++) part += qreg[i] * krow[lane + 32 * i];
        }
#pragma unroll
        for (int off = 16; off; off >>= 1)
            part += __shfl_down_sync(0xffffffffu, part, off);
        if (lane == 0) sh[warp][w] = (j >= 0) ? part * scale : -1e9f;
    }
    __syncwarp();

    float s0 = sh[warp][lane], s1 = sh[warp][lane + 32];
    float mx = fmaxf(s0, s1);
#pragma unroll
    for (int off = 16; off; off >>= 1)
        mx = fmaxf(mx, __shfl_xor_sync(0xffffffffu, mx, off));
    float e0 = expf(s0 - mx), e1 = expf(s1 - mx);
    float sum = e0 + e1;
#pragma unroll
    for (int off = 16; off; off >>= 1)
        sum += __shfl_xor_sync(0xffffffffu, sum, off);
    const float inv = 1.0f / sum;
    sh[warp][lane]      = e0 * inv;
    sh[warp][lane + 32] = e1 * inv;
    __syncwarp();

    float acc[16];
#pragma unroll
    for (int i = 0; i < 16; i++) acc[i] = 0.f;
    for (int w = 0; w < WW; w++) {
        const int j = j0 + w;
        if (j < 0) continue;
        const float p = sh[warp][w];
        const float* vrow = g_v + (base + j) * DD;
#pragma unroll
        for (int i = 0; i < 16; i++) acc[i] += p * vrow[lane + 32 * i];
    }
    float* orow = g_att + gq * DD;
#pragma unroll
    for (int i = 0; i < 16; i++) orow[lane + 32 * i] = acc[i];
}

// ===========================================================================
// Dual LayerNorm + add + exact GELU. One block (256 threads) per row.
// ===========================================================================
__global__ void __launch_bounds__(256) k_ln_gelu(
    const float* __restrict__ gamma, const float* __restrict__ beta,
    float* __restrict__ out)
{
    const int row = blockIdx.x;
    const int t   = threadIdx.x;
    const float* p = g_proj + row * DD;
    const float* r = g_r    + row * DD;

    float p0 = p[t], p1 = p[t + 256];
    float r0 = r[t], r1 = r[t + 256];

    float sp = p0 + p1, spp = p0 * p0 + p1 * p1;
    float sr = r0 + r1, srr = r0 * r0 + r1 * r1;

    __shared__ float red[8][4];
#pragma unroll
    for (int off = 16; off; off >>= 1) {
        sp  += __shfl_xor_sync(0xffffffffu, sp,  off);
        spp += __shfl_xor_sync(0xffffffffu, spp, off);
        sr  += __shfl_xor_sync(0xffffffffu, sr,  off);
        srr += __shfl_xor_sync(0xffffffffu, srr, off);
    }
    const int lane = t & 31, w = t >> 5;
    if (lane == 0) { red[w][0] = sp; red[w][1] = spp; red[w][2] = sr; red[w][3] = srr; }
    __syncthreads();
    float Sp = 0.f, Spp = 0.f, Sr = 0.f, Srr = 0.f;
#pragma unroll
    for (int i = 0; i < 8; i++) {
        Sp += red[i][0]; Spp += red[i][1]; Sr += red[i][2]; Srr += red[i][3];
    }

    const float invD = 1.0f / (float)DD;
    const float mup = Sp * invD;
    const float ip  = rsqrtf(Spp * invD - mup * mup + 1e-5f);
    const float mur = Sr * invD;
    const float ir  = rsqrtf(Srr * invD - mur * mur + 1e-5f);

    const float ga0 = gamma[t], ga1 = gamma[t + 256];
    const float be0 = beta[t],  be1 = beta[t + 256];

    const float y0 = (p0 - mup) * ip * ga0 + be0 + (r0 - mur) * ir * ga0 + be0;
    const float y1 = (p1 - mup) * ip * ga1 + be1 + (r1 - mur) * ir * ga1 + be1;

    out[row * DD + t]       = y0 * normcdff(y0);
    out[row * DD + t + 256] = y1 * normcdff(y1);
}

// ===========================================================================
extern "C" void kernel_launch(void* const* d_in, const int* in_sizes, int n_in,
                              void* d_out, int out_size)
{
    const float* x     = (const float*)d_in[0];
    const float* Wq    = (const float*)d_in[1];
    const float* bq    = (const float*)d_in[2];
    const float* Wk    = (const float*)d_in[3];
    const float* bk    = (const float*)d_in[4];
    const float* Wv    = (const float*)d_in[5];
    const float* bv    = (const float*)d_in[6];
    const float* Wo    = (const float*)d_in[7];
    const float* bo    = (const float*)d_in[8];
    const float* Wr    = (const float*)d_in[9];
    const float* br    = (const float*)d_in[10];
    const float* gamma = (const float*)d_in[11];
    const float* beta  = (const float*)d_in[12];
    float* out = (float*)d_out;

    k_gemm_qkv<<<dim3(4, 32, 3), 256>>>(x, Wq, bq, Wk, bk, Wv, bv);

    k_attn<<<MR / 32, 1024>>>();

    k_gemm_pr<<<dim3(4, 32, 2), 256>>>(x, Wo, bo, Wr, br);

    k_ln_gelu<<<MR, 256>>>(gamma, beta, out);
}

// round 7
// speedup vs baseline: 1.4617x; 1.2084x over previous
#include <cuda_runtime.h>
#include <math.h>
#include <stdint.h>

#define BB   2
#define SS   2048
#define DD   512
#define WW   64
#define MR   (BB*SS)     // 4096 rows

// Scratch (device globals — no allocation allowed)
__device__ float g_q[MR*DD];
__device__ float g_k[MR*DD];
__device__ float g_v[MR*DD];
__device__ float g_r[MR*DD];
__device__ float g_att[MR*DD];
__device__ float g_proj[MR*DD];

__device__ __forceinline__ uint32_t tf32r(float f) {
    uint32_t u; asm("cvt.rna.tf32.f32 %0, %1;" : "=r"(u) : "f"(f)); return u;
}

__device__ __forceinline__ void mma_tf32(float* c, const uint32_t* a, const uint32_t* b) {
    asm("mma.sync.aligned.m16n8k8.row.col.f32.tf32.tf32.f32 "
        "{%0,%1,%2,%3}, {%4,%5,%6,%7}, {%8,%9}, {%0,%1,%2,%3};"
        : "+f"(c[0]), "+f"(c[1]), "+f"(c[2]), "+f"(c[3])
        : "r"(a[0]), "r"(a[1]), "r"(a[2]), "r"(a[3]), "r"(b[0]), "r"(b[1]));
}

// ===========================================================================
// tf32 tensor-core GEMM: C[4096,512] = A[4096,512] @ W[512,512] + bias
// CTA tile 128x128, BK=32, 256 threads (8 warps, warp tile 32x64).
// (R3 version — single buffer, two syncs per chunk; measured fastest.)
// ===========================================================================
#define SKA 36
#define SKB 132

__device__ __forceinline__ void gemm_mma(const float* __restrict__ A,
                                         const float* __restrict__ W,
                                         const float* __restrict__ bias,
                                         float* __restrict__ C)
{
    __shared__ float As[128 * SKA];
    __shared__ float Bs[32 * SKB];

    const int tid  = threadIdx.x;
    const int lane = tid & 31;
    const int wid  = tid >> 5;
    const int g    = lane >> 2;
    const int tg   = lane & 3;
    const int m0   = blockIdx.y * 128;
    const int n0   = blockIdx.x * 128;
    const int wm   = (wid >> 1) * 32;
    const int wn   = (wid & 1) * 64;

    const int arow = tid >> 3;
    const int acol = (tid & 7) * 4;
    const int brow = tid >> 5;
    const int bcol = (tid & 31) * 4;

    const float* Ab = A + (m0 + arow) * DD + acol;
    const float* Wb = W + brow * DD + n0 + bcol;

    float4 pa[4], pb[4];
#pragma unroll
    for (int i = 0; i < 4; i++) {
        pa[i] = *(const float4*)(Ab + i * 32 * DD);
        pb[i] = *(const float4*)(Wb + i * 8 * DD);
    }

    float acc[2][8][4];
#pragma unroll
    for (int mt = 0; mt < 2; mt++)
#pragma unroll
        for (int nt = 0; nt < 8; nt++)
#pragma unroll
            for (int q = 0; q < 4; q++) acc[mt][nt][q] = 0.f;

    for (int ch = 0; ch < 16; ch++) {
        __syncthreads();
#pragma unroll
        for (int i = 0; i < 4; i++) {
            uint4 ua;
            ua.x = tf32r(pa[i].x); ua.y = tf32r(pa[i].y);
            ua.z = tf32r(pa[i].z); ua.w = tf32r(pa[i].w);
            *(uint4*)&As[(arow + 32 * i) * SKA + acol] = ua;
            uint4 ub;
            ub.x = tf32r(pb[i].x); ub.y = tf32r(pb[i].y);
            ub.z = tf32r(pb[i].z); ub.w = tf32r(pb[i].w);
            *(uint4*)&Bs[(brow + 8 * i) * SKB + bcol] = ub;
        }
        __syncthreads();

        if (ch < 15) {
            const float* Ab2 = Ab + (ch + 1) * 32;
            const float* Wb2 = Wb + (ch + 1) * 32 * DD;
#pragma unroll
            for (int i = 0; i < 4; i++) {
                pa[i] = *(const float4*)(Ab2 + i * 32 * DD);
                pb[i] = *(const float4*)(Wb2 + i * 8 * DD);
            }
        }

#pragma unroll
        for (int kk = 0; kk < 4; kk++) {
            const int kb = kk * 8;
            uint32_t af[2][4], bf[8][2];
#pragma unroll
            for (int mt = 0; mt < 2; mt++) {
                const int m = wm + mt * 16 + g;
                af[mt][0] = __float_as_uint(As[m * SKA + kb + tg]);
                af[mt][1] = __float_as_uint(As[(m + 8) * SKA + kb + tg]);
                af[mt][2] = __float_as_uint(As[m * SKA + kb + tg + 4]);
                af[mt][3] = __float_as_uint(As[(m + 8) * SKA + kb + tg + 4]);
            }
#pragma unroll
            for (int nt = 0; nt < 8; nt++) {
                const int n = wn + nt * 8 + g;
                bf[nt][0] = __float_as_uint(Bs[(kb + tg) * SKB + n]);
                bf[nt][1] = __float_as_uint(Bs[(kb + tg + 4) * SKB + n]);
            }
#pragma unroll
            for (int mt = 0; mt < 2; mt++)
#pragma unroll
                for (int nt = 0; nt < 8; nt++)
                    mma_tf32(acc[mt][nt], af[mt], bf[nt]);
        }
    }

#pragma unroll
    for (int nt = 0; nt < 8; nt++) {
        const int n = n0 + wn + nt * 8 + 2 * tg;
        const float2 bb = *(const float2*)&bias[n];
#pragma unroll
        for (int mt = 0; mt < 2; mt++) {
            const int m = m0 + wm + mt * 16 + g;
            float2 v0 = make_float2(acc[mt][nt][0] + bb.x, acc[mt][nt][1] + bb.y);
            float2 v1 = make_float2(acc[mt][nt][2] + bb.x, acc[mt][nt][3] + bb.y);
            *(float2*)&C[m * DD + n]       = v0;
            *(float2*)&C[(m + 8) * DD + n] = v1;
        }
    }
}

// Q/K/V projections only (R projection deferred to overlap the proj phase)
__global__ void __launch_bounds__(256, 2) k_gemm_qkv(
    const float* __restrict__ x,
    const float* Wq, const float* bq,
    const float* Wk, const float* bk,
    const float* Wv, const float* bv)
{
    const float* W; const float* bias; float* C;
    switch (blockIdx.z) {
        case 0:  W = Wq; bias = bq; C = g_q; break;
        case 1:  W = Wk; bias = bk; C = g_k; break;
        default: W = Wv; bias = bv; C = g_v; break;
    }
    gemm_mma(x, W, bias, C);
}

// proj (att@Wo) and r (x@Wr) fused in one launch — fills the half-idle
// proj phase with the independent r work.
__global__ void __launch_bounds__(256, 2) k_gemm_pr(
    const float* __restrict__ x,
    const float* Wo, const float* bo,
    const float* Wr, const float* br)
{
    if (blockIdx.z == 0) gemm_mma(g_att, Wo, bo, g_proj);
    else                 gemm_mma(x,     Wr, br, g_r);
}

// ===========================================================================
// Local windowed attention: one warp per query, 32 warps (1024 thr) per block.
// float4 loads: 4x fewer LDG (LSU-issue was the binding constraint).
// ===========================================================================
__global__ void __launch_bounds__(1024) k_attn()
{
    const int warp = threadIdx.x >> 5;
    const int lane = threadIdx.x & 31;
    const int gq   = blockIdx.x * 32 + warp;
    const int b    = gq / SS;
    const int s    = gq - b * SS;
    const int base = b * SS;

    // float4 view: row has 128 float4; lane covers f4-index lane + 32*i
    const float4* qrow = (const float4*)(g_q + gq * DD);
    float4 qreg[4];
#pragma unroll
    for (int i = 0; i < 4; i++) qreg[i] = qrow[lane + 32 * i];

    __shared__ float sh[32][WW];
    const int j0 = s - (WW - 1);
    const float scale = 0.044194173824159216f;   // 1/sqrt(512)

    for (int w = 0; w < WW; w++) {
        const int j = j0 + w;
        float part = 0.f;
        if (j >= 0) {
            const float4* krow = (const float4*)(g_k + (base + j) * DD);
#pragma unroll
            for (int i = 0; i < 4; i++) {
                const float4 kv = krow[lane + 32 * i];
                part += qreg[i].x * kv.x + qreg[i].y * kv.y
                      + qreg[i].z * kv.z + qreg[i].w * kv.w;
            }
        }
#pragma unroll
        for (int off = 16; off; off >>= 1)
            part += __shfl_down_sync(0xffffffffu, part, off);
        if (lane == 0) sh[warp][w] = (j >= 0) ? part * scale : -1e9f;
    }
    __syncwarp();

    float s0 = sh[warp][lane], s1 = sh[warp][lane + 32];
    float mx = fmaxf(s0, s1);
#pragma unroll
    for (int off = 16; off; off >>= 1)
        mx = fmaxf(mx, __shfl_xor_sync(0xffffffffu, mx, off));
    float e0 = expf(s0 - mx), e1 = expf(s1 - mx);
    float sum = e0 + e1;
#pragma unroll
    for (int off = 16; off; off >>= 1)
        sum += __shfl_xor_sync(0xffffffffu, sum, off);
    const float inv = 1.0f / sum;
    sh[warp][lane]      = e0 * inv;
    sh[warp][lane + 32] = e1 * inv;
    __syncwarp();

    float4 acc[4];
#pragma unroll
    for (int i = 0; i < 4; i++) acc[i] = make_float4(0.f, 0.f, 0.f, 0.f);
    for (int w = 0; w < WW; w++) {
        const int j = j0 + w;
        if (j < 0) continue;
        const float p = sh[warp][w];
        const float4* vrow = (const float4*)(g_v + (base + j) * DD);
#pragma unroll
        for (int i = 0; i < 4; i++) {
            const float4 vv = vrow[lane + 32 * i];
            acc[i].x += p * vv.x; acc[i].y += p * vv.y;
            acc[i].z += p * vv.z; acc[i].w += p * vv.w;
        }
    }
    float4* orow = (float4*)(g_att + gq * DD);
#pragma unroll
    for (int i = 0; i < 4; i++) orow[lane + 32 * i] = acc[i];
}

// ===========================================================================
// Dual LayerNorm + add + exact GELU. One block (256 threads) per row.
// ===========================================================================
__global__ void __launch_bounds__(256) k_ln_gelu(
    const float* __restrict__ gamma, const float* __restrict__ beta,
    float* __restrict__ out)
{
    const int row = blockIdx.x;
    const int t   = threadIdx.x;
    const float* p = g_proj + row * DD;
    const float* r = g_r    + row * DD;

    float p0 = p[t], p1 = p[t + 256];
    float r0 = r[t], r1 = r[t + 256];

    float sp = p0 + p1, spp = p0 * p0 + p1 * p1;
    float sr = r0 + r1, srr = r0 * r0 + r1 * r1;

    __shared__ float red[8][4];
#pragma unroll
    for (int off = 16; off; off >>= 1) {
        sp  += __shfl_xor_sync(0xffffffffu, sp,  off);
        spp += __shfl_xor_sync(0xffffffffu, spp, off);
        sr  += __shfl_xor_sync(0xffffffffu, sr,  off);
        srr += __shfl_xor_sync(0xffffffffu, srr, off);
    }
    const int lane = t & 31, w = t >> 5;
    if (lane == 0) { red[w][0] = sp; red[w][1] = spp; red[w][2] = sr; red[w][3] = srr; }
    __syncthreads();
    float Sp = 0.f, Spp = 0.f, Sr = 0.f, Srr = 0.f;
#pragma unroll
    for (int i = 0; i < 8; i++) {
        Sp += red[i][0]; Spp += red[i][1]; Sr += red[i][2]; Srr += red[i][3];
    }

    const float invD = 1.0f / (float)DD;
    const float mup = Sp * invD;
    const float ip  = rsqrtf(Spp * invD - mup * mup + 1e-5f);
    const float mur = Sr * invD;
    const float ir  = rsqrtf(Srr * invD - mur * mur + 1e-5f);

    const float ga0 = gamma[t], ga1 = gamma[t + 256];
    const float be0 = beta[t],  be1 = beta[t + 256];

    const float y0 = (p0 - mup) * ip * ga0 + be0 + (r0 - mur) * ir * ga0 + be0;
    const float y1 = (p1 - mup) * ip * ga1 + be1 + (r1 - mur) * ir * ga1 + be1;

    out[row * DD + t]       = y0 * normcdff(y0);
    out[row * DD + t + 256] = y1 * normcdff(y1);
}

// ===========================================================================
extern "C" void kernel_launch(void* const* d_in, const int* in_sizes, int n_in,
                              void* d_out, int out_size)
{
    const float* x     = (const float*)d_in[0];
    const float* Wq    = (const float*)d_in[1];
    const float* bq    = (const float*)d_in[2];
    const float* Wk    = (const float*)d_in[3];
    const float* bk    = (const float*)d_in[4];
    const float* Wv    = (const float*)d_in[5];
    const float* bv    = (const float*)d_in[6];
    const float* Wo    = (const float*)d_in[7];
    const float* bo    = (const float*)d_in[8];
    const float* Wr    = (const float*)d_in[9];
    const float* br    = (const float*)d_in[10];
    const float* gamma = (const float*)d_in[11];
    const float* beta  = (const float*)d_in[12];
    float* out = (float*)d_out;

    k_gemm_qkv<<<dim3(4, 32, 3), 256>>>(x, Wq, bq, Wk, bk, Wv, bv);

    k_attn<<<MR / 32, 1024>>>();

    k_gemm_pr<<<dim3(4, 32, 2), 256>>>(x, Wo, bo, Wr, br);

    k_ln_gelu<<<MR, 256>>>(gamma, beta, out);
}

// round 8
// speedup vs baseline: 1.5774x; 1.0791x over previous
#include <cuda_runtime.h>
#include <math.h>
#include <stdint.h>

#define BB   2
#define SS   2048
#define DD   512
#define WW   64
#define MR   (BB*SS)     // 4096 rows

// Scratch (device globals — no allocation allowed)
__device__ float g_q[MR*DD];
__device__ float g_k[MR*DD];
__device__ float g_v[MR*DD];
__device__ float g_r[MR*DD];
__device__ float g_att[MR*DD];
__device__ float g_proj[MR*DD];

__device__ __forceinline__ uint32_t tf32r(float f) {
    uint32_t u; asm("cvt.rna.tf32.f32 %0, %1;" : "=r"(u) : "f"(f)); return u;
}

__device__ __forceinline__ void mma_tf32(float* c, const uint32_t* a, const uint32_t* b) {
    asm("mma.sync.aligned.m16n8k8.row.col.f32.tf32.tf32.f32 "
        "{%0,%1,%2,%3}, {%4,%5,%6,%7}, {%8,%9}, {%0,%1,%2,%3};"
        : "+f"(c[0]), "+f"(c[1]), "+f"(c[2]), "+f"(c[3])
        : "r"(a[0]), "r"(a[1]), "r"(a[2]), "r"(a[3]), "r"(b[0]), "r"(b[1]));
}

// ===========================================================================
// tf32 tensor-core GEMM: C[4096,512] = A[4096,512] @ W[512,512] + bias
// CTA tile 128x128, BK=32, 128 threads (4 warps, warp tile 64x64).
// Fat warp tile: 32 LDS per 32 MMAs per k-step (was 24 per 16).
// ===========================================================================
#define SKA 36
#define SKB 132

__device__ __forceinline__ void gemm_mma(const float* __restrict__ A,
                                         const float* __restrict__ W,
                                         const float* __restrict__ bias,
                                         float* __restrict__ C)
{
    __shared__ float As[128 * SKA];
    __shared__ float Bs[32 * SKB];

    const int tid  = threadIdx.x;
    const int lane = tid & 31;
    const int wid  = tid >> 5;
    const int g    = lane >> 2;
    const int tg   = lane & 3;
    const int m0   = blockIdx.y * 128;
    const int n0   = blockIdx.x * 128;
    const int wm   = (wid >> 1) * 64;    // warp row offset (0/64)
    const int wn   = (wid & 1) * 64;     // warp col offset (0/64)

    // global load mapping (128 threads, 8 float4 each per operand per chunk)
    const int arow = tid >> 3;           // 0..15, +16 per i
    const int acol = (tid & 7) * 4;      // 0..28
    const int brow = tid >> 5;           // 0..3,  +4 per i
    const int bcol = (tid & 31) * 4;     // 0..124

    const float* Ab = A + (m0 + arow) * DD + acol;
    const float* Wb = W + brow * DD + n0 + bcol;

    float4 pa[8], pb[8];
#pragma unroll
    for (int i = 0; i < 8; i++) {
        pa[i] = *(const float4*)(Ab + i * 16 * DD);
        pb[i] = *(const float4*)(Wb + i * 4 * DD);
    }

    float acc[4][8][4];
#pragma unroll
    for (int mt = 0; mt < 4; mt++)
#pragma unroll
        for (int nt = 0; nt < 8; nt++)
#pragma unroll
            for (int q = 0; q < 4; q++) acc[mt][nt][q] = 0.f;

    for (int ch = 0; ch < 16; ch++) {
        __syncthreads();
#pragma unroll
        for (int i = 0; i < 8; i++) {
            uint4 ua;
            ua.x = tf32r(pa[i].x); ua.y = tf32r(pa[i].y);
            ua.z = tf32r(pa[i].z); ua.w = tf32r(pa[i].w);
            *(uint4*)&As[(arow + 16 * i) * SKA + acol] = ua;
            uint4 ub;
            ub.x = tf32r(pb[i].x); ub.y = tf32r(pb[i].y);
            ub.z = tf32r(pb[i].z); ub.w = tf32r(pb[i].w);
            *(uint4*)&Bs[(brow + 4 * i) * SKB + bcol] = ub;
        }
        __syncthreads();

        if (ch < 15) {
            const float* Ab2 = Ab + (ch + 1) * 32;
            const float* Wb2 = Wb + (ch + 1) * 32 * DD;
#pragma unroll
            for (int i = 0; i < 8; i++) {
                pa[i] = *(const float4*)(Ab2 + i * 16 * DD);
                pb[i] = *(const float4*)(Wb2 + i * 4 * DD);
            }
        }

#pragma unroll
        for (int kk = 0; kk < 4; kk++) {
            const int kb = kk * 8;
            uint32_t af[4][4], bf[8][2];
#pragma unroll
            for (int mt = 0; mt < 4; mt++) {
                const int m = wm + mt * 16 + g;
                af[mt][0] = __float_as_uint(As[m * SKA + kb + tg]);
                af[mt][1] = __float_as_uint(As[(m + 8) * SKA + kb + tg]);
                af[mt][2] = __float_as_uint(As[m * SKA + kb + tg + 4]);
                af[mt][3] = __float_as_uint(As[(m + 8) * SKA + kb + tg + 4]);
            }
#pragma unroll
            for (int nt = 0; nt < 8; nt++) {
                const int n = wn + nt * 8 + g;
                bf[nt][0] = __float_as_uint(Bs[(kb + tg) * SKB + n]);
                bf[nt][1] = __float_as_uint(Bs[(kb + tg + 4) * SKB + n]);
            }
#pragma unroll
            for (int mt = 0; mt < 4; mt++)
#pragma unroll
                for (int nt = 0; nt < 8; nt++)
                    mma_tf32(acc[mt][nt], af[mt], bf[nt]);
        }
    }

#pragma unroll
    for (int nt = 0; nt < 8; nt++) {
        const int n = n0 + wn + nt * 8 + 2 * tg;
        const float2 bb = *(const float2*)&bias[n];
#pragma unroll
        for (int mt = 0; mt < 4; mt++) {
            const int m = m0 + wm + mt * 16 + g;
            float2 v0 = make_float2(acc[mt][nt][0] + bb.x, acc[mt][nt][1] + bb.y);
            float2 v1 = make_float2(acc[mt][nt][2] + bb.x, acc[mt][nt][3] + bb.y);
            *(float2*)&C[m * DD + n]       = v0;
            *(float2*)&C[(m + 8) * DD + n] = v1;
        }
    }
}

// Q/K/V projections only (R projection deferred to overlap the proj phase)
__global__ void __launch_bounds__(128, 2) k_gemm_qkv(
    const float* __restrict__ x,
    const float* Wq, const float* bq,
    const float* Wk, const float* bk,
    const float* Wv, const float* bv)
{
    const float* W; const float* bias; float* C;
    switch (blockIdx.z) {
        case 0:  W = Wq; bias = bq; C = g_q; break;
        case 1:  W = Wk; bias = bk; C = g_k; break;
        default: W = Wv; bias = bv; C = g_v; break;
    }
    gemm_mma(x, W, bias, C);
}

// proj (att@Wo) and r (x@Wr) fused in one launch — fills the half-idle
// proj phase with the independent r work.
__global__ void __launch_bounds__(128, 2) k_gemm_pr(
    const float* __restrict__ x,
    const float* Wo, const float* bo,
    const float* Wr, const float* br)
{
    if (blockIdx.z == 0) gemm_mma(g_att, Wo, bo, g_proj);
    else                 gemm_mma(x,     Wr, br, g_r);
}

// ===========================================================================
// Local windowed attention: one warp per query, 32 warps (1024 thr) per block.
// float4 loads: 4x fewer LDG (LSU-issue was the binding constraint).
// ===========================================================================
__global__ void __launch_bounds__(1024) k_attn()
{
    const int warp = threadIdx.x >> 5;
    const int lane = threadIdx.x & 31;
    const int gq   = blockIdx.x * 32 + warp;
    const int b    = gq / SS;
    const int s    = gq - b * SS;
    const int base = b * SS;

    const float4* qrow = (const float4*)(g_q + gq * DD);
    float4 qreg[4];
#pragma unroll
    for (int i = 0; i < 4; i++) qreg[i] = qrow[lane + 32 * i];

    __shared__ float sh[32][WW];
    const int j0 = s - (WW - 1);
    const float scale = 0.044194173824159216f;   // 1/sqrt(512)

    for (int w = 0; w < WW; w++) {
        const int j = j0 + w;
        float part = 0.f;
        if (j >= 0) {
            const float4* krow = (const float4*)(g_k + (base + j) * DD);
#pragma unroll
            for (int i = 0; i < 4; i++) {
                const float4 kv = krow[lane + 32 * i];
                part += qreg[i].x * kv.x + qreg[i].y * kv.y
                      + qreg[i].z * kv.z + qreg[i].w * kv.w;
            }
        }
#pragma unroll
        for (int off = 16; off; off >>= 1)
            part += __shfl_down_sync(0xffffffffu, part, off);
        if (lane == 0) sh[warp][w] = (j >= 0) ? part * scale : -1e9f;
    }
    __syncwarp();

    float s0 = sh[warp][lane], s1 = sh[warp][lane + 32];
    float mx = fmaxf(s0, s1);
#pragma unroll
    for (int off = 16; off; off >>= 1)
        mx = fmaxf(mx, __shfl_xor_sync(0xffffffffu, mx, off));
    float e0 = expf(s0 - mx), e1 = expf(s1 - mx);
    float sum = e0 + e1;
#pragma unroll
    for (int off = 16; off; off >>= 1)
        sum += __shfl_xor_sync(0xffffffffu, sum, off);
    const float inv = 1.0f / sum;
    sh[warp][lane]      = e0 * inv;
    sh[warp][lane + 32] = e1 * inv;
    __syncwarp();

    float4 acc[4];
#pragma unroll
    for (int i = 0; i < 4; i++) acc[i] = make_float4(0.f, 0.f, 0.f, 0.f);
    for (int w = 0; w < WW; w++) {
        const int j = j0 + w;
        if (j < 0) continue;
        const float p = sh[warp][w];
        const float4* vrow = (const float4*)(g_v + (base + j) * DD);
#pragma unroll
        for (int i = 0; i < 4; i++) {
            const float4 vv = vrow[lane + 32 * i];
            acc[i].x += p * vv.x; acc[i].y += p * vv.y;
            acc[i].z += p * vv.z; acc[i].w += p * vv.w;
        }
    }
    float4* orow = (float4*)(g_att + gq * DD);
#pragma unroll
    for (int i = 0; i < 4; i++) orow[lane + 32 * i] = acc[i];
}

// ===========================================================================
// Dual LayerNorm + add + exact GELU. One block (256 threads) per row.
// ===========================================================================
__global__ void __launch_bounds__(256) k_ln_gelu(
    const float* __restrict__ gamma, const float* __restrict__ beta,
    float* __restrict__ out)
{
    const int row = blockIdx.x;
    const int t   = threadIdx.x;
    const float* p = g_proj + row * DD;
    const float* r = g_r    + row * DD;

    float p0 = p[t], p1 = p[t + 256];
    float r0 = r[t], r1 = r[t + 256];

    float sp = p0 + p1, spp = p0 * p0 + p1 * p1;
    float sr = r0 + r1, srr = r0 * r0 + r1 * r1;

    __shared__ float red[8][4];
#pragma unroll
    for (int off = 16; off; off >>= 1) {
        sp  += __shfl_xor_sync(0xffffffffu, sp,  off);
        spp += __shfl_xor_sync(0xffffffffu, spp, off);
        sr  += __shfl_xor_sync(0xffffffffu, sr,  off);
        srr += __shfl_xor_sync(0xffffffffu, srr, off);
    }
    const int lane = t & 31, w = t >> 5;
    if (lane == 0) { red[w][0] = sp; red[w][1] = spp; red[w][2] = sr; red[w][3] = srr; }
    __syncthreads();
    float Sp = 0.f, Spp = 0.f, Sr = 0.f, Srr = 0.f;
#pragma unroll
    for (int i = 0; i < 8; i++) {
        Sp += red[i][0]; Spp += red[i][1]; Sr += red[i][2]; Srr += red[i][3];
    }

    const float invD = 1.0f / (float)DD;
    const float mup = Sp * invD;
    const float ip  = rsqrtf(Spp * invD - mup * mup + 1e-5f);
    const float mur = Sr * invD;
    const float ir  = rsqrtf(Srr * invD - mur * mur + 1e-5f);

    const float ga0 = gamma[t], ga1 = gamma[t + 256];
    const float be0 = beta[t],  be1 = beta[t + 256];

    const float y0 = (p0 - mup) * ip * ga0 + be0 + (r0 - mur) * ir * ga0 + be0;
    const float y1 = (p1 - mup) * ip * ga1 + be1 + (r1 - mur) * ir * ga1 + be1;

    out[row * DD + t]       = y0 * normcdff(y0);
    out[row * DD + t + 256] = y1 * normcdff(y1);
}

// ===========================================================================
extern "C" void kernel_launch(void* const* d_in, const int* in_sizes, int n_in,
                              void* d_out, int out_size)
{
    const float* x     = (const float*)d_in[0];
    const float* Wq    = (const float*)d_in[1];
    const float* bq    = (const float*)d_in[2];
    const float* Wk    = (const float*)d_in[3];
    const float* bk    = (const float*)d_in[4];
    const float* Wv    = (const float*)d_in[5];
    const float* bv    = (const float*)d_in[6];
    const float* Wo    = (const float*)d_in[7];
    const float* bo    = (const float*)d_in[8];
    const float* Wr    = (const float*)d_in[9];
    const float* br    = (const float*)d_in[10];
    const float* gamma = (const float*)d_in[11];
    const float* beta  = (const float*)d_in[12];
    float* out = (float*)d_out;

    k_gemm_qkv<<<dim3(4, 32, 3), 128>>>(x, Wq, bq, Wk, bk, Wv, bv);

    k_attn<<<MR / 32, 1024>>>();

    k_gemm_pr<<<dim3(4, 32, 2), 128>>>(x, Wo, bo, Wr, br);

    k_ln_gelu<<<MR, 256>>>(gamma, beta, out);
}